// round 16
// baseline (speedup 1.0000x reference)
#include <cuda_runtime.h>
#include <cuda_fp16.h>
#include <cstdint>

// Problem constants
#define BB   16
#define CC   384      // C
#define CO   1536     // EXP*C
#define HW   1024     // 32*32
#define EMB_ 1024
#define NG   32
#define CPG  12
#define EPS_ 1e-5f

// ---------------- scratch (device globals) ---------------------------------
__device__ __align__(16) float  g_A[BB * CC];
__device__ __align__(16) float  g_D[BB * CC];
__device__ __align__(16) float  g_S[BB * CO];
__device__ __align__(16) float  g_T[BB * CO];
__device__ __align__(16) float  g_B1[BB * CO];                 // b1 + w1 @ D (fp32)
__device__ __align__(16) __half g_W1h[CO * CC];                // fp16 w1 [o][c]
__device__ __align__(16) __half g_W2h[CC * CO];                // fp16 w2 [o2][c']
__device__ __align__(16) __half g_Xh[(size_t)BB * CC * HW];    // fp16 a*x, NATURAL [b][c][s]
__device__ __align__(16) __half g_Hh[(size_t)BB * HW * CO];    // fp16 hidden [b][s][o]
__device__ int g_gn_done;                                      // gnstats arrival counter

// ---------------- helpers --------------------------------------------------
__device__ __forceinline__ void cpa16(uint32_t dst, const void* src) {
    asm volatile("cp.async.cg.shared.global [%0], [%1], 16;" :: "r"(dst), "l"(src));
}
#define CP_COMMIT() asm volatile("cp.async.commit_group;")
#define CP_WAIT1()  asm volatile("cp.async.wait_group 1;")

#define LDSM4(r0, r1, r2, r3, a)                                               \
    asm volatile("ldmatrix.sync.aligned.m8n8.x4.shared.b16 {%0,%1,%2,%3}, [%4];" \
        : "=r"(r0), "=r"(r1), "=r"(r2), "=r"(r3) : "r"(a))

#define LDSM4T(r0, r1, r2, r3, a)                                              \
    asm volatile("ldmatrix.sync.aligned.m8n8.x4.trans.shared.b16 {%0,%1,%2,%3}, [%4];" \
        : "=r"(r0), "=r"(r1), "=r"(r2), "=r"(r3) : "r"(a))

#define MMA_F16(d, a, b)                                                       \
    asm volatile(                                                              \
        "mma.sync.aligned.m16n8k16.row.col.f32.f16.f16.f32 "                   \
        "{%0,%1,%2,%3},{%4,%5,%6,%7},{%8,%9},{%0,%1,%2,%3};\n"                 \
        : "+f"((d)[0]), "+f"((d)[1]), "+f"((d)[2]), "+f"((d)[3])               \
        : "r"((a)[0]), "r"((a)[1]), "r"((a)[2]), "r"((a)[3]),                  \
          "r"((b)[0]), "r"((b)[1]))

// ---------------------------------------------------------------------------
// K_zero: reset the arrival counter (tiny; graph-capturable every launch).
// ---------------------------------------------------------------------------
__global__ void k_zero() { g_gn_done = 0; }

// ---------------------------------------------------------------------------
// K_setup: FUSED gnstats + emb + prep + biasfold + xh-convert, one kernel.
//   blocks [0, 512):      GroupNorm stats -> (A, D); bump g_gn_done
//   blocks [512, 896):    emb GEMV -> S, T                  (independent)
//   blocks [896, 2048):   w1/w2 -> fp16                     (independent)
//   blocks [2048, 2240):  b1' = b1 + w1@D     (spins on g_gn_done==512)
//   blocks [2240, 3776):  xh = fp16(A*x)      (spins on g_gn_done==512)
// Producers (bids 0..511) are scheduled first in bid order and never wait,
// so consumer spinning cannot deadlock.
// ---------------------------------------------------------------------------
__device__ __forceinline__ void wait_gn() {
    if (threadIdx.x == 0) {
        while (true) {
            int v;
            asm volatile("ld.acquire.gpu.b32 %0, [%1];"
                         : "=r"(v) : "l"(&g_gn_done));
            if (v == 512) break;
            __nanosleep(64);
        }
    }
    __syncthreads();
}

__global__ void __launch_bounds__(256)
k_setup(const float* __restrict__ x,
        const float* __restrict__ gnw,
        const float* __restrict__ gnb,
        const float* __restrict__ emb,
        const float* __restrict__ we,
        const float* __restrict__ be,
        const float* __restrict__ w1,
        const float* __restrict__ w2,
        const float* __restrict__ b1) {
    int bid = blockIdx.x;
    if (bid < 512) {
        // ---- GroupNorm stats ----
        int b = bid >> 5;
        int gi = bid & 31;
        const float4* p = (const float4*)(x + ((size_t)b * CC + (size_t)gi * CPG) * HW);
        float s = 0.f, ss = 0.f;
#pragma unroll
        for (int i = 0; i < 12; i++) {
            float4 v = p[threadIdx.x + i * 256];
            s  += v.x + v.y + v.z + v.w;
            ss += v.x * v.x + v.y * v.y + v.z * v.z + v.w * v.w;
        }
#pragma unroll
        for (int off = 16; off; off >>= 1) {
            s  += __shfl_xor_sync(0xffffffffu, s, off);
            ss += __shfl_xor_sync(0xffffffffu, ss, off);
        }
        __shared__ float sh[64];
        int w = threadIdx.x >> 5, l = threadIdx.x & 31;
        if (l == 0) { sh[w] = s; sh[32 + w] = ss; }
        __syncthreads();
        if (threadIdx.x < CPG) {
            float S = 0.f, SS = 0.f;
#pragma unroll
            for (int i = 0; i < 8; i++) { S += sh[i]; SS += sh[32 + i]; }
            float mean = S * (1.0f / 12288.0f);
            float var  = SS * (1.0f / 12288.0f) - mean * mean;
            float rstd = rsqrtf(var + EPS_);
            int cch = gi * CPG + threadIdx.x;
            float wv = gnw[cch], bv = gnb[cch];
            g_A[b * CC + cch] = rstd * wv;
            g_D[b * CC + cch] = bv - mean * rstd * wv;
        }
        __syncthreads();
        if (threadIdx.x == 0) {
            __threadfence();                       // publish g_A/g_D
            atomicAdd(&g_gn_done, 1);
        }
    } else if (bid < 896) {
        // ---- emb GEMV: warp per o, all 16 batches ----
        int o = (bid - 512) * 8 + (threadIdx.x >> 5);   // 0..3071
        int lane = threadIdx.x & 31;
        const float4* w4 = (const float4*)(we + (size_t)o * EMB_);
        float4 wv[8];
#pragma unroll
        for (int i = 0; i < 8; i++) wv[i] = w4[lane + i * 32];
        float bev = be[o];

        float mine = 0.f;
#pragma unroll
        for (int b = 0; b < BB; b++) {
            const float4* e4 = (const float4*)(emb + (size_t)b * EMB_);
            float s = 0.f;
#pragma unroll
            for (int i = 0; i < 8; i++) {
                float4 ev = e4[lane + i * 32];
                s += ev.x * wv[i].x + ev.y * wv[i].y + ev.z * wv[i].z + ev.w * wv[i].w;
            }
#pragma unroll
            for (int off = 16; off; off >>= 1)
                s += __shfl_xor_sync(0xffffffffu, s, off);
            if (lane == b) mine = s;
        }
        if (lane < BB) {
            if (o < CO) g_S[lane * CO + o] = 1.0f + mine + bev;
            else        g_T[lane * CO + (o - CO)] = mine + bev;
        }
    } else if (bid < 2048) {
        // ---- weights -> fp16 ----
        const int N1 = CO * CC / 4;
        int t = (bid - 896) * 256 + threadIdx.x;
        const float4* src = (t < N1) ? (const float4*)w1 : (const float4*)w2;
        int i = (t < N1) ? t : t - N1;
        float4 v = src[i];
        __half2 lo = __floats2half2_rn(v.x, v.y);
        __half2 hi = __floats2half2_rn(v.z, v.w);
        uint2 pk = make_uint2(*(uint32_t*)&lo, *(uint32_t*)&hi);
        if (t < N1) ((uint2*)g_W1h)[i] = pk;
        else        ((uint2*)g_W2h)[i] = pk;
    } else if (bid < 2240) {
        // ---- bias fold (needs g_D): warp per o, w1 row in regs ----
        int o = (bid - 2048) * 8 + (threadIdx.x >> 5);  // 0..1535
        int lane = threadIdx.x & 31;
        const float4* w4 = (const float4*)(w1 + (size_t)o * CC);
        float4 wv[3];
#pragma unroll
        for (int i = 0; i < 3; i++) wv[i] = w4[lane + i * 32];
        float bv = b1[o];
        wait_gn();
        float mine = 0.f;
#pragma unroll
        for (int b = 0; b < BB; b++) {
            const float* dr = g_D + b * CC;
            float s = 0.f;
#pragma unroll
            for (int i = 0; i < 3; i++) {
                int c = (lane + i * 32) * 4;
                s += wv[i].x * dr[c] + wv[i].y * dr[c + 1]
                   + wv[i].z * dr[c + 2] + wv[i].w * dr[c + 3];
            }
#pragma unroll
            for (int off = 16; off; off >>= 1)
                s += __shfl_xor_sync(0xffffffffu, s, off);
            if (lane == b) mine = s;
        }
        if (lane < BB) g_B1[lane * CO + o] = bv + mine;
    } else {
        // ---- xh convert (needs g_A): 4 float4 per thread, coalesced ----
        int base = (bid - 2240) * 1024 + threadIdx.x;
        float4 v[4];
#pragma unroll
        for (int i = 0; i < 4; i++)
            v[i] = ((const float4*)x)[base + i * 256];   // prefetch before wait
        wait_gn();
#pragma unroll
        for (int i = 0; i < 4; i++) {
            int idx = base + i * 256;
            float a = g_A[idx >> 8];
            __half2 lo = __floats2half2_rn(a * v[i].x, a * v[i].y);
            __half2 hi = __floats2half2_rn(a * v[i].z, a * v[i].w);
            ((uint2*)g_Xh)[idx] = make_uint2(*(uint32_t*)&lo, *(uint32_t*)&hi);
        }
    }
}

// ---------------------------------------------------------------------------
// GEMM geometry (measured-best R14 config, unchanged): CTA 128x128, BK=64,
// NSTAGE=3, one barrier per k-tile:
//   CP_WAIT1 -> __syncthreads -> fill((kt+2)%3) -> commit -> compute(kt%3)
// ---------------------------------------------------------------------------
#define PITCH   144
#define TILE_K64 (128 * PITCH)          // 18432 B
#define STG2_B  (2 * TILE_K64)          // 36864 B
#define NSTAGE  3
#define SMEM2_BYTES (NSTAGE * STG2_B)   // 110592 B

#define PITCH_A1 272
#define TILE_A1  (64 * PITCH_A1)        // 17408 B
#define STG1_B   (TILE_A1 + TILE_K64)   // 35840 B
#define SMEM1_BYTES (NSTAGE * STG1_B)   // 107520 B

extern __shared__ uint8_t dsm8[];

__device__ __forceinline__ void fill_g2(uint32_t sdst,
        const __half* Asrc, const __half* Bsrc, int tid) {
#pragma unroll
    for (int i = 0; i < 8; i++) {
        int ch = tid + i * 256;
        int isB = ch >> 10;
        int base = ch & 1023;
        int r = base >> 3, cb = base & 7;
        const __half* src = isB ? (Bsrc + (size_t)r * CO + cb * 8)
                                : (Asrc + (size_t)r * CO + cb * 8);
        cpa16(sdst + isB * TILE_K64 + r * PITCH + cb * 16, src);
    }
}

__device__ __forceinline__ void fill_g1(uint32_t sdst,
        const __half* Ax, const __half* Bw, int tid) {
#pragma unroll
    for (int i = 0; i < 8; i++) {
        int ch = tid + i * 256;
        if (ch < 1024) {                   // A: 64 rows x 16 chunks
            int r = ch >> 4, cb = ch & 15;
            cpa16(sdst + r * PITCH_A1 + cb * 16, Ax + (size_t)r * HW + cb * 8);
        } else {                           // B: 128 rows x 8 chunks
            int base = ch - 1024;
            int r = base >> 3, cb = base & 7;
            cpa16(sdst + TILE_A1 + r * PITCH + cb * 16,
                  Bw + (size_t)r * CC + cb * 8);
        }
    }
}

// ---------------------------------------------------------------------------
// K_gemm1: D[s,o] = xh^T @ w1^T via trans-ldmatrix A. K=CC, KT=6.
// ---------------------------------------------------------------------------
__global__ void __launch_bounds__(256, 2)
k_gemm1() {
    __shared__ float sb1[128], sS[128], sT[128];
    const int tid = threadIdx.x;
    const int b = blockIdx.z;
    const int o0 = blockIdx.y * 128;
    const int s0 = blockIdx.x * 128;
    if (tid < 128) {
        int o = o0 + tid;
        sb1[tid] = g_B1[b * CO + o];
        sS[tid]  = g_S[b * CO + o];
        sT[tid]  = g_T[b * CO + o];
    }
    __syncthreads();

    const __half* Abase = g_Xh + (size_t)b * CC * HW + s0;
    const __half* Bbase = g_W1h + (size_t)o0 * CC;

    const int lane = tid & 31, warp = tid >> 5;
    const int wm = warp & 3, wn = warp >> 2;
    float acc[2][8][4];
#pragma unroll
    for (int i = 0; i < 2; i++)
#pragma unroll
        for (int j = 0; j < 8; j++)
#pragma unroll
            for (int e = 0; e < 4; e++) acc[i][j][e] = 0.f;

    uint32_t smb = (uint32_t)__cvta_generic_to_shared(dsm8);
    uint32_t aoff = (uint32_t)(((lane & 7) + ((lane >> 4) << 3)) * PITCH_A1
                               + ((lane >> 3) & 1) * 16);
    uint32_t boff = (uint32_t)((wn * 64 + (lane & 7) + ((lane >> 4) << 3)) * PITCH
                               + ((lane >> 3) & 1) * 16);

    const int KT = CC / 64;   // 6
#pragma unroll
    for (int s = 0; s < NSTAGE - 1; s++) {
        fill_g1(smb + s * STG1_B, Abase + (size_t)s * 64 * HW, Bbase + s * 64, tid);
        CP_COMMIT();
    }

    int s_cur = 0, s_fill = NSTAGE - 1;
    for (int kt = 0; kt < KT; kt++) {
        CP_WAIT1();
        __syncthreads();

        if (kt + NSTAGE - 1 < KT)
            fill_g1(smb + s_fill * STG1_B,
                    Abase + (size_t)(kt + NSTAGE - 1) * 64 * HW,
                    Bbase + (size_t)(kt + NSTAGE - 1) * 64, tid);
        CP_COMMIT();

        uint32_t sA = smb + s_cur * STG1_B;
        uint32_t sB = sA + TILE_A1;
#pragma unroll
        for (int kk = 0; kk < 4; kk++) {
            uint32_t af[2][4], bf[8][2];
#pragma unroll
            for (int mt = 0; mt < 2; mt++)
                LDSM4T(af[mt][0], af[mt][1], af[mt][2], af[mt][3],
                       sA + aoff + kk * 16 * PITCH_A1 + (wm * 32 + mt * 16) * 2);
#pragma unroll
            for (int p = 0; p < 4; p++) {
                uint32_t r0, r1, r2, r3;
                LDSM4(r0, r1, r2, r3, sB + boff + p * 16 * PITCH + kk * 32);
                bf[2 * p][0] = r0;  bf[2 * p][1] = r1;
                bf[2 * p + 1][0] = r2; bf[2 * p + 1][1] = r3;
            }
#pragma unroll
            for (int mt = 0; mt < 2; mt++)
#pragma unroll
                for (int nt = 0; nt < 8; nt++)
                    MMA_F16(acc[mt][nt], af[mt], bf[nt]);
        }
        s_cur  = (s_cur  == NSTAGE - 1) ? 0 : s_cur + 1;
        s_fill = (s_fill == NSTAGE - 1) ? 0 : s_fill + 1;
    }

    const int g = lane >> 2, t = lane & 3;
    __half* Hb = g_Hh + ((size_t)b * HW + s0) * CO + o0;
#pragma unroll
    for (int mt = 0; mt < 2; mt++)
#pragma unroll
        for (int h = 0; h < 2; h++) {
            int s_loc = wm * 32 + mt * 16 + h * 8 + g;
            __half* Hrow = Hb + (size_t)s_loc * CO;
#pragma unroll
            for (int nt = 0; nt < 8; nt++) {
                int oc = wn * 64 + nt * 8 + t * 2;
                float v0 = acc[mt][nt][h * 2 + 0] + sb1[oc];
                float v1 = acc[mt][nt][h * 2 + 1] + sb1[oc + 1];
                float h0 = v0 / (1.0f + __expf(-v0));
                float h1 = v1 / (1.0f + __expf(-v1));
                __half2 pk = __floats2half2_rn(h0 * sS[oc] + sT[oc],
                                               h1 * sS[oc + 1] + sT[oc + 1]);
                *(uint32_t*)(Hrow + oc) = *(uint32_t*)&pk;
            }
        }
}

// ---------------------------------------------------------------------------
// K_gemm2: D[o2,s] = w2 @ H^T; K=CO, KT=24. Measured-best config unchanged.
// ---------------------------------------------------------------------------
__global__ void __launch_bounds__(256, 2)
k_gemm2(const float* __restrict__ b2,
        const float* __restrict__ x,
        float* __restrict__ out) {
    __shared__ float sb2[128];
    const int tid = threadIdx.x;
    const int b = blockIdx.z;
    const int o20 = blockIdx.y * 128;
    const int s0 = blockIdx.x * 128;
    if (tid < 128) sb2[tid] = b2[o20 + tid];
    __syncthreads();

    const __half* Abase = g_W2h + (size_t)o20 * CO;
    const __half* Bbase = g_Hh + ((size_t)b * HW + s0) * CO;

    const int lane = tid & 31, warp = tid >> 5;
    const int wm = warp & 3, wn = warp >> 2;
    float acc[2][8][4];
#pragma unroll
    for (int i = 0; i < 2; i++)
#pragma unroll
        for (int j = 0; j < 8; j++)
#pragma unroll
            for (int e = 0; e < 4; e++) acc[i][j][e] = 0.f;

    uint32_t smb = (uint32_t)__cvta_generic_to_shared(dsm8);
    uint32_t aoff = (uint32_t)((wm * 32 + (lane & 15)) * PITCH + (lane >> 4) * 16);
    uint32_t boff = (uint32_t)((wn * 64 + (lane & 7) + ((lane >> 4) << 3)) * PITCH
                               + ((lane >> 3) & 1) * 16);

    const int KT = CO / 64;   // 24
#pragma unroll
    for (int s = 0; s < NSTAGE - 1; s++) {
        fill_g2(smb + s * STG2_B, Abase + s * 64, Bbase + s * 64, tid);
        CP_COMMIT();
    }

    int s_cur = 0, s_fill = NSTAGE - 1;
    for (int kt = 0; kt < KT; kt++) {
        CP_WAIT1();
        __syncthreads();

        if (kt + NSTAGE - 1 < KT)
            fill_g2(smb + s_fill * STG2_B,
                    Abase + (size_t)(kt + NSTAGE - 1) * 64,
                    Bbase + (size_t)(kt + NSTAGE - 1) * 64, tid);
        CP_COMMIT();

        uint32_t sA = smb + s_cur * STG2_B;
        uint32_t sB = sA + TILE_K64;
#pragma unroll
        for (int kk = 0; kk < 4; kk++) {
            uint32_t af[2][4], bf[8][2];
#pragma unroll
            for (int mt = 0; mt < 2; mt++)
                LDSM4(af[mt][0], af[mt][1], af[mt][2], af[mt][3],
                      sA + aoff + mt * 16 * PITCH + kk * 32);
#pragma unroll
            for (int p = 0; p < 4; p++) {
                uint32_t r0, r1, r2, r3;
                LDSM4(r0, r1, r2, r3, sB + boff + p * 16 * PITCH + kk * 32);
                bf[2 * p][0] = r0;  bf[2 * p][1] = r1;
                bf[2 * p + 1][0] = r2; bf[2 * p + 1][1] = r3;
            }
#pragma unroll
            for (int mt = 0; mt < 2; mt++)
#pragma unroll
                for (int nt = 0; nt < 8; nt++)
                    MMA_F16(acc[mt][nt], af[mt], bf[nt]);
        }
        s_cur  = (s_cur  == NSTAGE - 1) ? 0 : s_cur + 1;
        s_fill = (s_fill == NSTAGE - 1) ? 0 : s_fill + 1;
    }

    const int g = lane >> 2, t = lane & 3;
#pragma unroll
    for (int mt = 0; mt < 2; mt++)
#pragma unroll
        for (int h = 0; h < 2; h++) {
            int mloc = wm * 32 + mt * 16 + h * 8 + g;
            int o2 = o20 + mloc;
            float bv = sb2[mloc];
            const float* xrow = x + (size_t)b * CC * HW + (size_t)o2 * HW + s0;
            float* orow = out + (size_t)b * CC * HW + (size_t)o2 * HW + s0;
#pragma unroll
            for (int nt = 0; nt < 8; nt++) {
                int sc = wn * 64 + nt * 8 + t * 2;
                float2 xr = *(const float2*)(xrow + sc);
                float2 ov;
                ov.x = acc[mt][nt][h * 2 + 0] + bv + xr.x;
                ov.y = acc[mt][nt][h * 2 + 1] + bv + xr.y;
                *(float2*)(orow + sc) = ov;
            }
        }
}

// ---------------------------------------------------------------------------
extern "C" void kernel_launch(void* const* d_in, const int* in_sizes, int n_in,
                              void* d_out, int out_size) {
    const float* x    = (const float*)d_in[0];
    const float* emb  = (const float*)d_in[1];
    const float* gn_w = (const float*)d_in[2];
    const float* gn_b = (const float*)d_in[3];
    const float* w1   = (const float*)d_in[4];
    const float* b1   = (const float*)d_in[5];
    const float* we   = (const float*)d_in[6];
    const float* be   = (const float*)d_in[7];
    const float* w2   = (const float*)d_in[8];
    const float* b2   = (const float*)d_in[9];
    float* out = (float*)d_out;

    static bool attr_set = false;
    if (!attr_set) {
        cudaFuncSetAttribute(k_gemm1, cudaFuncAttributeMaxDynamicSharedMemorySize, SMEM1_BYTES);
        cudaFuncSetAttribute(k_gemm2, cudaFuncAttributeMaxDynamicSharedMemorySize, SMEM2_BYTES);
        attr_set = true;
    }

    k_zero<<<1, 1>>>();
    // 512 gnstats + 384 emb + 1152 prep + 192 biasfold + 1536 xh blocks
    k_setup<<<3776, 256>>>(x, gn_w, gn_b, emb, we, be, w1, w2, b1);
    k_gemm1<<<dim3(HW / 128, CO / 128, BB), 256, SMEM1_BYTES>>>();
    k_gemm2<<<dim3(HW / 128, CC / 128, BB), 256, SMEM2_BYTES>>>(b2, x, out);
}

// round 17
// speedup vs baseline: 1.0424x; 1.0424x over previous
#include <cuda_runtime.h>
#include <cuda_fp16.h>
#include <cstdint>

// Problem constants
#define BB   16
#define CC   384      // C
#define CO   1536     // EXP*C
#define HW   1024     // 32*32
#define EMB_ 1024
#define NG   32
#define CPG  12
#define EPS_ 1e-5f

// ---------------- scratch (device globals) ---------------------------------
__device__ __align__(16) float  g_A[BB * CC];
__device__ __align__(16) float  g_D[BB * CC];
__device__ __align__(16) float  g_S[BB * CO];
__device__ __align__(16) float  g_T[BB * CO];
__device__ __align__(16) float  g_B1[BB * CO];                 // b1 + w1 @ D (fp32)
__device__ __align__(16) __half g_W1h[CO * CC];                // fp16 w1 [o][c]
__device__ __align__(16) __half g_W2h[CC * CO];                // fp16 w2 [o2][c']
__device__ __align__(16) __half g_Xh[(size_t)BB * CC * HW];    // fp16 a*x, NATURAL [b][c][s]
__device__ __align__(16) __half g_Hh[(size_t)BB * HW * CO];    // fp16 hidden [b][s][o]
__device__ int g_gn_done;                                      // gnstats arrivals
__device__ int g_h_done[BB * 8];                               // gemm1 arrivals per (b, s-tile)

// ---------------- helpers --------------------------------------------------
__device__ __forceinline__ void cpa16(uint32_t dst, const void* src) {
    asm volatile("cp.async.cg.shared.global [%0], [%1], 16;" :: "r"(dst), "l"(src));
}
#define CP_COMMIT() asm volatile("cp.async.commit_group;")
#define CP_WAIT1()  asm volatile("cp.async.wait_group 1;")

#define LDSM4(r0, r1, r2, r3, a)                                               \
    asm volatile("ldmatrix.sync.aligned.m8n8.x4.shared.b16 {%0,%1,%2,%3}, [%4];" \
        : "=r"(r0), "=r"(r1), "=r"(r2), "=r"(r3) : "r"(a))

#define LDSM4T(r0, r1, r2, r3, a)                                              \
    asm volatile("ldmatrix.sync.aligned.m8n8.x4.trans.shared.b16 {%0,%1,%2,%3}, [%4];" \
        : "=r"(r0), "=r"(r1), "=r"(r2), "=r"(r3) : "r"(a))

#define MMA_F16(d, a, b)                                                       \
    asm volatile(                                                              \
        "mma.sync.aligned.m16n8k16.row.col.f32.f16.f16.f32 "                   \
        "{%0,%1,%2,%3},{%4,%5,%6,%7},{%8,%9},{%0,%1,%2,%3};\n"                 \
        : "+f"((d)[0]), "+f"((d)[1]), "+f"((d)[2]), "+f"((d)[3])               \
        : "r"((a)[0]), "r"((a)[1]), "r"((a)[2]), "r"((a)[3]),                  \
          "r"((b)[0]), "r"((b)[1]))

__device__ __forceinline__ int ld_acq(const int* p) {
    int v;
    asm volatile("ld.acquire.gpu.b32 %0, [%1];" : "=r"(v) : "l"(p));
    return v;
}

// ---------------------------------------------------------------------------
// K_zero: reset all arrival counters (graph-replay deterministic).
// ---------------------------------------------------------------------------
__global__ void k_zero() {
    g_gn_done = 0;
    for (int i = 0; i < BB * 8; i++) g_h_done[i] = 0;
}

// ---------------------------------------------------------------------------
// K_setup: FUSED gnstats + emb + prep + biasfold + xh-convert (R16, proven).
// ---------------------------------------------------------------------------
__device__ __forceinline__ void wait_gn() {
    if (threadIdx.x == 0) {
        while (ld_acq(&g_gn_done) != 512) __nanosleep(64);
    }
    __syncthreads();
}

__global__ void __launch_bounds__(256)
k_setup(const float* __restrict__ x,
        const float* __restrict__ gnw,
        const float* __restrict__ gnb,
        const float* __restrict__ emb,
        const float* __restrict__ we,
        const float* __restrict__ be,
        const float* __restrict__ w1,
        const float* __restrict__ w2,
        const float* __restrict__ b1) {
    int bid = blockIdx.x;
    if (bid < 512) {
        // ---- GroupNorm stats ----
        int b = bid >> 5;
        int gi = bid & 31;
        const float4* p = (const float4*)(x + ((size_t)b * CC + (size_t)gi * CPG) * HW);
        float s = 0.f, ss = 0.f;
#pragma unroll
        for (int i = 0; i < 12; i++) {
            float4 v = p[threadIdx.x + i * 256];
            s  += v.x + v.y + v.z + v.w;
            ss += v.x * v.x + v.y * v.y + v.z * v.z + v.w * v.w;
        }
#pragma unroll
        for (int off = 16; off; off >>= 1) {
            s  += __shfl_xor_sync(0xffffffffu, s, off);
            ss += __shfl_xor_sync(0xffffffffu, ss, off);
        }
        __shared__ float sh[64];
        int w = threadIdx.x >> 5, l = threadIdx.x & 31;
        if (l == 0) { sh[w] = s; sh[32 + w] = ss; }
        __syncthreads();
        if (threadIdx.x < CPG) {
            float S = 0.f, SS = 0.f;
#pragma unroll
            for (int i = 0; i < 8; i++) { S += sh[i]; SS += sh[32 + i]; }
            float mean = S * (1.0f / 12288.0f);
            float var  = SS * (1.0f / 12288.0f) - mean * mean;
            float rstd = rsqrtf(var + EPS_);
            int cch = gi * CPG + threadIdx.x;
            float wv = gnw[cch], bv = gnb[cch];
            g_A[b * CC + cch] = rstd * wv;
            g_D[b * CC + cch] = bv - mean * rstd * wv;
        }
        __syncthreads();
        if (threadIdx.x == 0) {
            __threadfence();
            atomicAdd(&g_gn_done, 1);
        }
    } else if (bid < 896) {
        // ---- emb GEMV ----
        int o = (bid - 512) * 8 + (threadIdx.x >> 5);
        int lane = threadIdx.x & 31;
        const float4* w4 = (const float4*)(we + (size_t)o * EMB_);
        float4 wv[8];
#pragma unroll
        for (int i = 0; i < 8; i++) wv[i] = w4[lane + i * 32];
        float bev = be[o];
        float mine = 0.f;
#pragma unroll
        for (int b = 0; b < BB; b++) {
            const float4* e4 = (const float4*)(emb + (size_t)b * EMB_);
            float s = 0.f;
#pragma unroll
            for (int i = 0; i < 8; i++) {
                float4 ev = e4[lane + i * 32];
                s += ev.x * wv[i].x + ev.y * wv[i].y + ev.z * wv[i].z + ev.w * wv[i].w;
            }
#pragma unroll
            for (int off = 16; off; off >>= 1)
                s += __shfl_xor_sync(0xffffffffu, s, off);
            if (lane == b) mine = s;
        }
        if (lane < BB) {
            if (o < CO) g_S[lane * CO + o] = 1.0f + mine + bev;
            else        g_T[lane * CO + (o - CO)] = mine + bev;
        }
    } else if (bid < 2048) {
        // ---- weights -> fp16 ----
        const int N1 = CO * CC / 4;
        int t = (bid - 896) * 256 + threadIdx.x;
        const float4* src = (t < N1) ? (const float4*)w1 : (const float4*)w2;
        int i = (t < N1) ? t : t - N1;
        float4 v = src[i];
        __half2 lo = __floats2half2_rn(v.x, v.y);
        __half2 hi = __floats2half2_rn(v.z, v.w);
        uint2 pk = make_uint2(*(uint32_t*)&lo, *(uint32_t*)&hi);
        if (t < N1) ((uint2*)g_W1h)[i] = pk;
        else        ((uint2*)g_W2h)[i] = pk;
    } else if (bid < 2240) {
        // ---- bias fold (needs g_D) ----
        int o = (bid - 2048) * 8 + (threadIdx.x >> 5);
        int lane = threadIdx.x & 31;
        const float4* w4 = (const float4*)(w1 + (size_t)o * CC);
        float4 wv[3];
#pragma unroll
        for (int i = 0; i < 3; i++) wv[i] = w4[lane + i * 32];
        float bv = b1[o];
        wait_gn();
        float mine = 0.f;
#pragma unroll
        for (int b = 0; b < BB; b++) {
            const float* dr = g_D + b * CC;
            float s = 0.f;
#pragma unroll
            for (int i = 0; i < 3; i++) {
                int c = (lane + i * 32) * 4;
                s += wv[i].x * dr[c] + wv[i].y * dr[c + 1]
                   + wv[i].z * dr[c + 2] + wv[i].w * dr[c + 3];
            }
#pragma unroll
            for (int off = 16; off; off >>= 1)
                s += __shfl_xor_sync(0xffffffffu, s, off);
            if (lane == b) mine = s;
        }
        if (lane < BB) g_B1[lane * CO + o] = bv + mine;
    } else {
        // ---- xh convert (needs g_A) ----
        int base = (bid - 2240) * 1024 + threadIdx.x;
        float4 v[4];
#pragma unroll
        for (int i = 0; i < 4; i++)
            v[i] = ((const float4*)x)[base + i * 256];
        wait_gn();
#pragma unroll
        for (int i = 0; i < 4; i++) {
            int idx = base + i * 256;
            float a = g_A[idx >> 8];
            __half2 lo = __floats2half2_rn(a * v[i].x, a * v[i].y);
            __half2 hi = __floats2half2_rn(a * v[i].z, a * v[i].w);
            ((uint2*)g_Xh)[idx] = make_uint2(*(uint32_t*)&lo, *(uint32_t*)&hi);
        }
    }
}

// ---------------------------------------------------------------------------
// GEMM geometry (measured-best): CTA 128x128, BK=64, NSTAGE=3,
// one barrier per k-tile: CP_WAIT1 -> sync -> fill -> commit -> compute.
// ---------------------------------------------------------------------------
#define PITCH   144
#define TILE_K64 (128 * PITCH)          // 18432 B
#define STG2_B  (2 * TILE_K64)          // 36864 B
#define NSTAGE  3
#define SMEM2_BYTES (NSTAGE * STG2_B)   // 110592 B

#define PITCH_A1 272
#define TILE_A1  (64 * PITCH_A1)        // 17408 B
#define STG1_B   (TILE_A1 + TILE_K64)   // 35840 B
#define SMEM_MAX SMEM2_BYTES            // fused kernel uses the max

extern __shared__ uint8_t dsm8[];

__device__ __forceinline__ void fill_g2(uint32_t sdst,
        const __half* Asrc, const __half* Bsrc, int tid) {
#pragma unroll
    for (int i = 0; i < 8; i++) {
        int ch = tid + i * 256;
        int isB = ch >> 10;
        int base = ch & 1023;
        int r = base >> 3, cb = base & 7;
        const __half* src = isB ? (Bsrc + (size_t)r * CO + cb * 8)
                                : (Asrc + (size_t)r * CO + cb * 8);
        cpa16(sdst + isB * TILE_K64 + r * PITCH + cb * 16, src);
    }
}

__device__ __forceinline__ void fill_g1(uint32_t sdst,
        const __half* Ax, const __half* Bw, int tid) {
#pragma unroll
    for (int i = 0; i < 8; i++) {
        int ch = tid + i * 256;
        if (ch < 1024) {                   // A: 64 rows x 16 chunks
            int r = ch >> 4, cb = ch & 15;
            cpa16(sdst + r * PITCH_A1 + cb * 16, Ax + (size_t)r * HW + cb * 8);
        } else {                           // B: 128 rows x 8 chunks
            int base = ch - 1024;
            int r = base >> 3, cb = base & 7;
            cpa16(sdst + TILE_A1 + r * PITCH + cb * 16,
                  Bw + (size_t)r * CC + cb * 8);
        }
    }
}

// ---------------------------------------------------------------------------
// K_gemm12: FUSED gemm1 + gemm2, one launch, arrival-counter dependency.
//   bids [0, 1536):    gemm1 role, order (b, s_t, o_t): 12 o-tiles per
//                      (b,s_t) are contiguous -> early unlock.
//   bids [1536, 1920): gemm2 role, order (b, s_t, o2_t); spins until
//                      g_h_done[b*8+s_t]==12, then H reads are safe.
// Producers never wait and precede consumers in bid order: deadlock-free.
// ---------------------------------------------------------------------------
__global__ void __launch_bounds__(256, 2)
k_gemm12(const float* __restrict__ b2,
         const float* __restrict__ x,
         float* __restrict__ out) {
    const int tid = threadIdx.x;
    const int lane = tid & 31, warp = tid >> 5;
    const int wm = warp & 3, wn = warp >> 2;
    uint32_t smb = (uint32_t)__cvta_generic_to_shared(dsm8);

    float acc[2][8][4];
#pragma unroll
    for (int i = 0; i < 2; i++)
#pragma unroll
        for (int j = 0; j < 8; j++)
#pragma unroll
            for (int e = 0; e < 4; e++) acc[i][j][e] = 0.f;

    if (blockIdx.x < 1536) {
        // =================== gemm1 role ===================
        int bid = blockIdx.x;
        int b = bid / 96;
        int rem = bid % 96;
        int s_t = rem / 12;
        int o_t = rem % 12;
        int s0 = s_t * 128, o0 = o_t * 128;

        __shared__ float sb1[128], sS[128], sT[128];
        if (tid < 128) {
            int o = o0 + tid;
            sb1[tid] = g_B1[b * CO + o];
            sS[tid]  = g_S[b * CO + o];
            sT[tid]  = g_T[b * CO + o];
        }
        __syncthreads();

        const __half* Abase = g_Xh + (size_t)b * CC * HW + s0;
        const __half* Bbase = g_W1h + (size_t)o0 * CC;

        uint32_t aoff = (uint32_t)(((lane & 7) + ((lane >> 4) << 3)) * PITCH_A1
                                   + ((lane >> 3) & 1) * 16);
        uint32_t boff = (uint32_t)((wn * 64 + (lane & 7) + ((lane >> 4) << 3)) * PITCH
                                   + ((lane >> 3) & 1) * 16);

        const int KT = CC / 64;   // 6
#pragma unroll
        for (int s = 0; s < NSTAGE - 1; s++) {
            fill_g1(smb + s * STG1_B, Abase + (size_t)s * 64 * HW, Bbase + s * 64, tid);
            CP_COMMIT();
        }
        int s_cur = 0, s_fill = NSTAGE - 1;
        for (int kt = 0; kt < KT; kt++) {
            CP_WAIT1();
            __syncthreads();
            if (kt + NSTAGE - 1 < KT)
                fill_g1(smb + s_fill * STG1_B,
                        Abase + (size_t)(kt + NSTAGE - 1) * 64 * HW,
                        Bbase + (size_t)(kt + NSTAGE - 1) * 64, tid);
            CP_COMMIT();

            uint32_t sA = smb + s_cur * STG1_B;
            uint32_t sB = sA + TILE_A1;
#pragma unroll
            for (int kk = 0; kk < 4; kk++) {
                uint32_t af[2][4], bf[8][2];
#pragma unroll
                for (int mt = 0; mt < 2; mt++)
                    LDSM4T(af[mt][0], af[mt][1], af[mt][2], af[mt][3],
                           sA + aoff + kk * 16 * PITCH_A1 + (wm * 32 + mt * 16) * 2);
#pragma unroll
                for (int p = 0; p < 4; p++) {
                    uint32_t r0, r1, r2, r3;
                    LDSM4(r0, r1, r2, r3, sB + boff + p * 16 * PITCH + kk * 32);
                    bf[2 * p][0] = r0;  bf[2 * p][1] = r1;
                    bf[2 * p + 1][0] = r2; bf[2 * p + 1][1] = r3;
                }
#pragma unroll
                for (int mt = 0; mt < 2; mt++)
#pragma unroll
                    for (int nt = 0; nt < 8; nt++)
                        MMA_F16(acc[mt][nt], af[mt], bf[nt]);
            }
            s_cur  = (s_cur  == NSTAGE - 1) ? 0 : s_cur + 1;
            s_fill = (s_fill == NSTAGE - 1) ? 0 : s_fill + 1;
        }

        const int g = lane >> 2, t = lane & 3;
        __half* Hb = g_Hh + ((size_t)b * HW + s0) * CO + o0;
#pragma unroll
        for (int mt = 0; mt < 2; mt++)
#pragma unroll
            for (int h = 0; h < 2; h++) {
                int s_loc = wm * 32 + mt * 16 + h * 8 + g;
                __half* Hrow = Hb + (size_t)s_loc * CO;
#pragma unroll
                for (int nt = 0; nt < 8; nt++) {
                    int oc = wn * 64 + nt * 8 + t * 2;
                    float v0 = acc[mt][nt][h * 2 + 0] + sb1[oc];
                    float v1 = acc[mt][nt][h * 2 + 1] + sb1[oc + 1];
                    float h0 = v0 / (1.0f + __expf(-v0));
                    float h1 = v1 / (1.0f + __expf(-v1));
                    __half2 pk = __floats2half2_rn(h0 * sS[oc] + sT[oc],
                                                   h1 * sS[oc + 1] + sT[oc + 1]);
                    *(uint32_t*)(Hrow + oc) = *(uint32_t*)&pk;
                }
            }
        // signal: this (b, s_t) tile's o0-slice of H is complete
        __threadfence();
        __syncthreads();
        if (tid == 0) atomicAdd(&g_h_done[b * 8 + s_t], 1);
    } else {
        // =================== gemm2 role ===================
        int idx = blockIdx.x - 1536;
        int b = idx / 24;
        int rem = idx % 24;
        int s_t = rem / 3;
        int o2t = rem % 3;
        int s0 = s_t * 128, o20 = o2t * 128;

        __shared__ float sb2[128];
        if (tid < 128) sb2[tid] = b2[o20 + tid];

        // wait for all 12 gemm1 o-tiles of (b, s_t)
        if (tid == 0) {
            while (ld_acq(&g_h_done[b * 8 + s_t]) != 12) __nanosleep(128);
        }
        __syncthreads();

        const __half* Abase = g_W2h + (size_t)o20 * CO;
        const __half* Bbase = g_Hh + ((size_t)b * HW + s0) * CO;

        uint32_t aoff = (uint32_t)((wm * 32 + (lane & 15)) * PITCH + (lane >> 4) * 16);
        uint32_t boff = (uint32_t)((wn * 64 + (lane & 7) + ((lane >> 4) << 3)) * PITCH
                                   + ((lane >> 3) & 1) * 16);

        const int KT = CO / 64;   // 24
#pragma unroll
        for (int s = 0; s < NSTAGE - 1; s++) {
            fill_g2(smb + s * STG2_B, Abase + s * 64, Bbase + s * 64, tid);
            CP_COMMIT();
        }
        int s_cur = 0, s_fill = NSTAGE - 1;
        for (int kt = 0; kt < KT; kt++) {
            CP_WAIT1();
            __syncthreads();
            if (kt + NSTAGE - 1 < KT)
                fill_g2(smb + s_fill * STG2_B,
                        Abase + (size_t)(kt + NSTAGE - 1) * 64,
                        Bbase + (size_t)(kt + NSTAGE - 1) * 64, tid);
            CP_COMMIT();

            uint32_t sA = smb + s_cur * STG2_B;
            uint32_t sB = sA + TILE_K64;
#pragma unroll
            for (int kk = 0; kk < 4; kk++) {
                uint32_t af[2][4], bf[8][2];
#pragma unroll
                for (int mt = 0; mt < 2; mt++)
                    LDSM4(af[mt][0], af[mt][1], af[mt][2], af[mt][3],
                          sA + aoff + mt * 16 * PITCH + kk * 32);
#pragma unroll
                for (int p = 0; p < 4; p++) {
                    uint32_t r0, r1, r2, r3;
                    LDSM4(r0, r1, r2, r3, sB + boff + p * 16 * PITCH + kk * 32);
                    bf[2 * p][0] = r0;  bf[2 * p][1] = r1;
                    bf[2 * p + 1][0] = r2; bf[2 * p + 1][1] = r3;
                }
#pragma unroll
                for (int mt = 0; mt < 2; mt++)
#pragma unroll
                    for (int nt = 0; nt < 8; nt++)
                        MMA_F16(acc[mt][nt], af[mt], bf[nt]);
            }
            s_cur  = (s_cur  == NSTAGE - 1) ? 0 : s_cur + 1;
            s_fill = (s_fill == NSTAGE - 1) ? 0 : s_fill + 1;
        }

        const int g = lane >> 2, t = lane & 3;
#pragma unroll
        for (int mt = 0; mt < 2; mt++)
#pragma unroll
            for (int h = 0; h < 2; h++) {
                int mloc = wm * 32 + mt * 16 + h * 8 + g;
                int o2 = o20 + mloc;
                float bv = sb2[mloc];
                const float* xrow = x + (size_t)b * CC * HW + (size_t)o2 * HW + s0;
                float* orow = out + (size_t)b * CC * HW + (size_t)o2 * HW + s0;
#pragma unroll
                for (int nt = 0; nt < 8; nt++) {
                    int sc = wn * 64 + nt * 8 + t * 2;
                    float2 xr = *(const float2*)(xrow + sc);
                    float2 ov;
                    ov.x = acc[mt][nt][h * 2 + 0] + bv + xr.x;
                    ov.y = acc[mt][nt][h * 2 + 1] + bv + xr.y;
                    *(float2*)(orow + sc) = ov;
                }
            }
    }
}

// ---------------------------------------------------------------------------
extern "C" void kernel_launch(void* const* d_in, const int* in_sizes, int n_in,
                              void* d_out, int out_size) {
    const float* x    = (const float*)d_in[0];
    const float* emb  = (const float*)d_in[1];
    const float* gn_w = (const float*)d_in[2];
    const float* gn_b = (const float*)d_in[3];
    const float* w1   = (const float*)d_in[4];
    const float* b1   = (const float*)d_in[5];
    const float* we   = (const float*)d_in[6];
    const float* be   = (const float*)d_in[7];
    const float* w2   = (const float*)d_in[8];
    const float* b2   = (const float*)d_in[9];
    float* out = (float*)d_out;

    static bool attr_set = false;
    if (!attr_set) {
        cudaFuncSetAttribute(k_gemm12, cudaFuncAttributeMaxDynamicSharedMemorySize, SMEM_MAX);
        attr_set = true;
    }

    k_zero<<<1, 1>>>();
    // 512 gnstats + 384 emb + 1152 prep + 192 biasfold + 1536 xh blocks
    k_setup<<<3776, 256>>>(x, gn_w, gn_b, emb, we, be, w1, w2, b1);
    // fused gemm1 (1536 CTAs) + gemm2 (384 CTAs)
    k_gemm12<<<1920, 256, SMEM_MAX>>>(b2, x, out);
}